// round 4
// baseline (speedup 1.0000x reference)
#include <cuda_runtime.h>
#include <cstdint>
#include <cstddef>

// RWW whole-brain sim, 8-CTA cluster, Con_Mtx register-resident (128 f32/thread).
// R4: NO cluster-wide barrier in the loop. Point-to-point sync:
//   - 16 mbarriers per CTA: [buffer 0/1][source CTA 0..7], arrive count = 16.
//   - 16 sender lanes/CTA pack 4 regions into a float4 via warp shuffles
//     (no smem staging, no __syncthreads) and push st.shared::cluster.v4
//     + mbarrier.arrive.release.cluster to all 8 CTAs (incl. self).
//   - Consumers wait only on the 2 source barriers their columns need;
//     matvec split in halves to overlap with the second source's arrival.
// Safety of 2-buffer reuse: every warp waits (lockstep) on all 8 sources,
// and every source's 16 sender lanes span all 8 of its warps, so a completed
// barrier transitively proves the source CTA finished its previous reads.

#define NREG    512
#define NSTEPS  20000
#define NCTAS   8
#define NTHR    256

// padded x layout: quarter stride QF floats (QF*4 = 2576 B == 16 mod 128 ->
// the 4 column-quarter lanes of a warp hit distinct 16B bank groups, 8-way bcast)
#define QF 644
#define PF 2576
#define XBYTES   (2 * PF * 4)              // 20608 B, two parity buffers
#define MBAR_OFF XBYTES                    // 16 mbarriers * 8 B
#define SMEM_BYTES (XBYTES + 128)

__device__ __forceinline__ unsigned long long ffma2(
    unsigned long long a, unsigned long long b, unsigned long long c) {
    unsigned long long d;
    asm("fma.rn.f32x2 %0, %1, %2, %3;" : "=l"(d) : "l"(a), "l"(b), "l"(c));
    return d;
}
__device__ __forceinline__ float fsum2(unsigned long long a) {
    float2 f = *reinterpret_cast<float2*>(&a);
    return f.x + f.y;
}
__device__ __forceinline__ void mbar_wait(uint32_t mb, uint32_t par) {
    asm volatile(
        "{\n\t"
        ".reg .pred P;\n"
        "WL_%=:\n\t"
        "mbarrier.try_wait.parity.acquire.cluster.shared::cta.b64 P, [%0], %1, 0x989680;\n\t"
        "@!P bra WL_%=;\n\t"
        "}" :: "r"(mb), "r"(par) : "memory");
}

__device__ __forceinline__ float Hfun(float I, float a, float b, float d, float bigc) {
    float x     = fmaf(a, I, -b);
    float numer = fabsf(x) + 1e-9f;
    float neg   = -d * x;
    float e     = __expf(fminf(neg, 51.0f));
    float den_s = fabsf(1.0f - e) + 1e-9f * d;
    float den_b = fabsf(1.0f - bigc * neg) + 1e-9f * d;
    float denom = (neg > 50.0f) ? den_b : den_s;
    return __fdividef(numer, denom);
}

extern __shared__ float smx[];

__global__ void __launch_bounds__(NTHR, 1) __cluster_dims__(NCTAS, 1, 1)
rww_kernel(const float* __restrict__ init_state,   // (512, 2)
           const float* __restrict__ Con,          // (512, 512) row-major
           const float* __restrict__ vofT,         // (20000, 512)
           float* __restrict__ out)                // 1024 final + 20000*1024 hist
{
    const int tid  = (int)threadIdx.x;
    const int cta  = (int)blockIdx.x;         // cluster rank (grid = 1 cluster)
    const int lane = tid & 31;
    const int wrp  = tid >> 5;                 // warp 0..7
    const int r    = tid >> 2;                 // local row 0..63
    const int q    = tid & 3;                  // column quarter 0..3
    const int j    = cta * 64 + r;             // global region of this row

    uint32_t sb;
    asm("{ .reg .u64 t; cvta.to.shared.u64 t, %1; cvt.u32.u64 %0, t; }"
        : "=r"(sb) : "l"(smx));

    // ---- 16 mbarriers: [b][s] at MBAR_OFF + b*64 + s*8, count=16 ----
    if (tid < 16)
        asm volatile("mbarrier.init.shared.b64 [%0], %1;"
                     :: "r"(sb + MBAR_OFF + (uint32_t)(tid * 8)), "r"(16));

    // ---- Con row segment -> 64 packed f32x2 registers (128 fp32) ----
    unsigned long long c64[64];
    {
        const ulonglong2* src =
            (const ulonglong2*)(Con + (size_t)j * NREG + (size_t)q * 128);
        #pragma unroll
        for (int it = 0; it < 32; ++it) {
            ulonglong2 t2 = src[it];
            c64[2*it] = t2.x; c64[2*it+1] = t2.y;
        }
    }

    // ---- init x buffer 0 locally in every CTA ----
    for (int k = tid; k < NREG; k += NTHR)
        smx[(k >> 7) * QF + (k & 127)] = init_state[2 * k];

    float sE = init_state[2 * j];
    float sI = init_state[2 * j + 1];

    // ---- sender setup: lanes 0..15 of each warp ----
    // lane sends chunk sc (regions wrp*8+sc*4 .. +3) to cluster rank sdst.
    const bool sender = (lane < 16);
    const int  sdst   = lane & 7;
    const int  sc     = (lane >> 3) & 1;
    uint32_t remX0 = 0, remX1 = 0, remB0 = 0, remB1 = 0;
    if (sender) {
        int g = cta * 64 + wrp * 8 + sc * 4;                 // first region of chunk
        uint32_t lx = sb + (uint32_t)((((g >> 7) * QF) + (g & 127)) * 4);
        uint32_t lb = sb + MBAR_OFF + (uint32_t)(cta * 8);
        asm("mapa.shared::cluster.u32 %0, %1, %2;" : "=r"(remX0) : "r"(lx), "r"(sdst));
        asm("mapa.shared::cluster.u32 %0, %1, %2;" : "=r"(remX1) : "r"(lx + (uint32_t)(PF*4)), "r"(sdst));
        asm("mapa.shared::cluster.u32 %0, %1, %2;" : "=r"(remB0) : "r"(lb), "r"(sdst));
        asm("mapa.shared::cluster.u32 %0, %1, %2;" : "=r"(remB1) : "r"(lb + 64u), "r"(sdst));
    }

    // consumer barrier addresses (this CTA, sources 2q / 2q+1), per buffer
    const uint32_t mbq0 = sb + MBAR_OFF + (uint32_t)(16 * q);        // buffer 0
    const uint32_t mbq1 = mbq0 + 64u;                                // buffer 1

    // one full rendezvous: barrier inits + buffer-0 preload visible
    asm volatile("barrier.cluster.arrive.aligned;" ::: "memory");
    asm volatile("barrier.cluster.wait.aligned;"   ::: "memory");

    // noise pipeline, 2 deep
    float vc = __ldg(vofT + j);
    float vn = __ldg(vofT + NREG + j);
    float2* outv = (float2*)out;

    int ph0 = 0, ph1 = 0;   // wait parity per buffer

    for (int t = 0; t < NSTEPS; ++t) {
        const int b = t & 1;                 // buffer read this step
        const uint32_t mbA = b ? mbq1 : mbq0;
        const uint32_t par = (uint32_t)(b ? ph1 : ph0);

        // prefetch noise for t+2 (deep pipeline)
        int t2 = t + 2; if (t2 >= NSTEPS) t2 = NSTEPS - 1;
        float vf = __ldg(vofT + (size_t)t2 * NREG + j);

        const ulonglong2* x2 = (const ulonglong2*)
            ((const char*)smx + (b ? PF * 4 : 0) + q * (QF * 4));

        unsigned long long a0 = 0ULL, a1 = 0ULL, a2 = 0ULL, a3 = 0ULL;

        // ---- first half: columns of source 2q ----
        if (t) mbar_wait(mbA, par);
        #pragma unroll
        for (int it = 0; it < 8; ++it) {
            ulonglong2 xa = x2[2*it];
            ulonglong2 xb = x2[2*it+1];
            a0 = ffma2(c64[4*it+0], xa.x, a0);
            a1 = ffma2(c64[4*it+1], xa.y, a1);
            a2 = ffma2(c64[4*it+2], xb.x, a2);
            a3 = ffma2(c64[4*it+3], xb.y, a3);
        }
        // ---- second half: columns of source 2q+1 ----
        if (t) mbar_wait(mbA + 8u, par);
        #pragma unroll
        for (int it = 8; it < 16; ++it) {
            ulonglong2 xa = x2[2*it];
            ulonglong2 xb = x2[2*it+1];
            a0 = ffma2(c64[4*it+0], xa.x, a0);
            a1 = ffma2(c64[4*it+1], xa.y, a1);
            a2 = ffma2(c64[4*it+2], xb.x, a2);
            a3 = ffma2(c64[4*it+3], xb.y, a3);
        }
        if (t) { if (b) ph1 ^= 1; else ph0 ^= 1; }

        float acc = (fsum2(a0) + fsum2(a1)) + (fsum2(a2) + fsum2(a3));
        acc += __shfl_xor_sync(0xffffffffu, acc, 1);
        acc += __shfl_xor_sync(0xffffffffu, acc, 2);
        // all 4 lanes of each row hold the full dot product

        // ---- epilogue (replicated on all lanes, bit-identical) ----
        float I_E = 0.382f  + 0.21f * sE + 3.0f * acc - sI;   // LAMBDA=0 folded
        float I_I = 0.2674f + 0.15f * sE - sI;
        float rE = Hfun(I_E, 310.0f, 125.0f, 0.16f,  1e9f);
        float rI = Hfun(I_I, 615.0f, 177.0f, 0.087f, 1e5f);
        float dE = -sE * 0.01f + (1.0f - sE) * 6.41e-4f * rE + 0.01f * vc;
        float dI = -sI * 0.1f  + 1.0e-3f * rI + 0.01f * vc;
        sE = fmaf(1e-4f, dE, sE);
        sI = fmaf(1e-4f, dI, sI);

        // ---- pack 4 regions into a float4 via shuffles (no smem staging) ----
        const int sbase = 16 * sc;   // rows 4*sc .. 4*sc+3 live at lanes 16sc+4k
        float4 sv;
        sv.x = __shfl_sync(0xffffffffu, sE, sbase + 0);
        sv.y = __shfl_sync(0xffffffffu, sE, sbase + 4);
        sv.z = __shfl_sync(0xffffffffu, sE, sbase + 8);
        sv.w = __shfl_sync(0xffffffffu, sE, sbase + 12);

        // ---- send to all 8 CTAs (incl self): 16B store + release-arrive ----
        if (sender && (t + 1 < NSTEPS)) {
            uint32_t rx = b ? remX0 : remX1;   // target buffer b^1
            uint32_t rb = b ? remB0 : remB1;   // barrier[b^1][cta] at dst
            asm volatile("st.shared::cluster.v4.f32 [%0], {%1, %2, %3, %4};"
                         :: "r"(rx), "f"(sv.x), "f"(sv.y), "f"(sv.z), "f"(sv.w)
                         : "memory");
            asm volatile("mbarrier.arrive.release.cluster.shared::cluster.b64 _, [%0];"
                         :: "r"(rb) : "memory");
        }

        // history (off critical path)
        if (q == 0)
            outv[512 + (size_t)t * NREG + j] = make_float2(sE, sI);

        vc = vn; vn = vf;
    }

    if (q == 0) outv[j] = make_float2(sE, sI);

    // drain: no CTA exits while peers might still target its SMEM
    asm volatile("barrier.cluster.arrive.aligned;" ::: "memory");
    asm volatile("barrier.cluster.wait.aligned;"   ::: "memory");
}

extern "C" void kernel_launch(void* const* d_in, const int* in_sizes, int n_in,
                              void* d_out, int out_size) {
    const float* init = nullptr;
    const float* con  = nullptr;
    const float* v    = nullptr;
    for (int i = 0; i < n_in; ++i) {
        if      (in_sizes[i] == NREG * 2)      init = (const float*)d_in[i];
        else if (in_sizes[i] == NREG * NREG)   con  = (const float*)d_in[i];
        else if (in_sizes[i] == NSTEPS * NREG) v    = (const float*)d_in[i];
    }
    rww_kernel<<<NCTAS, NTHR, SMEM_BYTES>>>(init, con, v, (float*)d_out);
    (void)out_size;
}

// round 5
// speedup vs baseline: 2.4175x; 2.4175x over previous
#include <cuda_runtime.h>
#include <cstdint>
#include <cstddef>

// RWW whole-brain sim, 8-CTA cluster, Con_Mtx register-resident.
// R5: 512 threads/CTA (4 warps/SMSP -> 2x issue width), 64 cols/thread,
//     shuffle-pack + direct st.shared::cluster.v4 out of the epilogue
//     (no smem staging), barrier.cluster sync (the only scheme that
//     measured well: R2/R4 proved per-lane mbarrier arrives serialize).

#define NREG    512
#define NSTEPS  20000
#define NCTAS   8
#define NTHR    512

// x layout: eighth stride EF floats. EF*4 = 272 B == 16 mod 128 ->
// the 8 column-eighth lane groups of a warp hit 8 distinct 16B bank
// groups (4-way broadcast within each group) => conflict-free LDS.128.
#define EF 68
#define PF 544                      // floats per parity buffer (8*68)
#define SMEM_BYTES (2 * PF * 4)     // 4352 B

__device__ __forceinline__ unsigned long long ffma2(
    unsigned long long a, unsigned long long b, unsigned long long c) {
    unsigned long long d;
    asm("fma.rn.f32x2 %0, %1, %2, %3;" : "=l"(d) : "l"(a), "l"(b), "l"(c));
    return d;
}
__device__ __forceinline__ float fsum2(unsigned long long a) {
    float2 f = *reinterpret_cast<float2*>(&a);
    return f.x + f.y;
}

__device__ __forceinline__ float Hfun(float I, float a, float b, float d, float bigc) {
    float x     = fmaf(a, I, -b);
    float numer = fabsf(x) + 1e-9f;
    float neg   = -d * x;
    float e     = __expf(fminf(neg, 51.0f));
    float den_s = fabsf(1.0f - e) + 1e-9f * d;
    float den_b = fabsf(1.0f - bigc * neg) + 1e-9f * d;
    float denom = (neg > 50.0f) ? den_b : den_s;
    return __fdividef(numer, denom);
}

extern __shared__ float smx[];

__global__ void __launch_bounds__(NTHR, 1) __cluster_dims__(NCTAS, 1, 1)
rww_kernel(const float* __restrict__ init_state,   // (512, 2)
           const float* __restrict__ Con,          // (512, 512) row-major
           const float* __restrict__ vofT,         // (20000, 512)
           float* __restrict__ out)                // 1024 final + 20000*1024 hist
{
    const int tid  = (int)threadIdx.x;
    const int cta  = (int)blockIdx.x;          // cluster rank
    const int lane = tid & 31;
    const int wrp  = tid >> 5;                 // warp 0..15 (owns rows 4w..4w+3)
    const int r    = tid >> 3;                 // local row 0..63
    const int q    = tid & 7;                  // column eighth 0..7
    const int j    = cta * 64 + r;             // global region of this row

    uint32_t sb;
    asm("{ .reg .u64 t; cvta.to.shared.u64 t, %1; cvt.u32.u64 %0, t; }"
        : "=r"(sb) : "l"(smx));

    // ---- Con row segment: cols q*64..q*64+63 -> 32 packed f32x2 regs ----
    unsigned long long c64[32];
    {
        const ulonglong2* src =
            (const ulonglong2*)(Con + (size_t)j * NREG + (size_t)q * 64);
        #pragma unroll
        for (int it = 0; it < 16; ++it) {
            ulonglong2 t2 = src[it];
            c64[2*it] = t2.x; c64[2*it+1] = t2.y;
        }
    }

    // ---- init x buffer 0 locally: x[k] @ (k>>6)*EF + (k&63) ----
    if (tid < NREG)
        smx[(tid >> 6) * EF + (tid & 63)] = init_state[2 * tid];

    float sE = init_state[2 * j];
    float sI = init_state[2 * j + 1];

    // ---- sender setup: lanes 0..7 of each warp send warp's 4 rows ----
    // regions g = cta*64 + 4*wrp .. +3 live at floats cta*EF + 4*wrp (16B aligned)
    const bool sender = (lane < 8);
    uint32_t remX0 = 0, remX1 = 0;
    if (sender) {
        uint32_t lx = sb + (uint32_t)((cta * EF + 4 * wrp) * 4);
        asm("mapa.shared::cluster.u32 %0, %1, %2;" : "=r"(remX0) : "r"(lx), "r"(lane));
        asm("mapa.shared::cluster.u32 %0, %1, %2;"
            : "=r"(remX1) : "r"(lx + (uint32_t)(PF * 4)), "r"(lane));
    }

    __syncthreads();   // local buffer-0 init visible to this CTA

    // one-time rendezvous (cheap insurance: all CTAs resident + inited)
    asm volatile("barrier.cluster.arrive.aligned;" ::: "memory");
    asm volatile("barrier.cluster.wait.aligned;"   ::: "memory");

    // noise pipeline, 2 deep (8 lanes per row load the same address)
    float vc = __ldg(vofT + j);
    float vn = __ldg(vofT + NREG + j);
    float2* outv = (float2*)out;

    for (int t = 0; t < NSTEPS; ++t) {
        const int b = t & 1;

        // ---- matvec: 64 cols/thread, Con in regs, x from smem (f32x2) ----
        const ulonglong2* x2 = (const ulonglong2*)
            ((const char*)smx + (b ? PF * 4 : 0) + q * (EF * 4));
        unsigned long long a0 = 0ULL, a1 = 0ULL, a2 = 0ULL, a3 = 0ULL;
        #pragma unroll
        for (int it = 0; it < 8; ++it) {
            ulonglong2 xa = x2[2*it];
            ulonglong2 xb = x2[2*it+1];
            a0 = ffma2(c64[4*it+0], xa.x, a0);
            a1 = ffma2(c64[4*it+1], xa.y, a1);
            a2 = ffma2(c64[4*it+2], xb.x, a2);
            a3 = ffma2(c64[4*it+3], xb.y, a3);
        }
        float acc = (fsum2(a0) + fsum2(a1)) + (fsum2(a2) + fsum2(a3));
        acc += __shfl_xor_sync(0xffffffffu, acc, 1);
        acc += __shfl_xor_sync(0xffffffffu, acc, 2);
        acc += __shfl_xor_sync(0xffffffffu, acc, 4);
        // all 8 lanes of each row hold the full dot product

        // ---- epilogue (replicated, bit-identical across the 8 lanes) ----
        float I_E = 0.382f  + 0.21f * sE + 3.0f * acc - sI;   // LAMBDA=0 folded
        float I_I = 0.2674f + 0.15f * sE - sI;
        float rE = Hfun(I_E, 310.0f, 125.0f, 0.16f,  1e9f);
        float rI = Hfun(I_I, 615.0f, 177.0f, 0.087f, 1e5f);
        float dE = -sE * 0.01f + (1.0f - sE) * 6.41e-4f * rE + 0.01f * vc;
        float dI = -sI * 0.1f  + 1.0e-3f * rI + 0.01f * vc;
        sE = fmaf(1e-4f, dE, sE);
        sI = fmaf(1e-4f, dI, sI);

        // ---- pack this warp's 4 rows (lead lanes 0,8,16,24) via shuffles ----
        float4 sv;
        sv.x = __shfl_sync(0xffffffffu, sE, 0);
        sv.y = __shfl_sync(0xffffffffu, sE, 8);
        sv.z = __shfl_sync(0xffffffffu, sE, 16);
        sv.w = __shfl_sync(0xffffffffu, sE, 24);

        // ---- direct remote stores to buffer b^1 of all 8 CTAs ----
        if (sender) {
            uint32_t rx = b ? remX0 : remX1;
            asm volatile("st.shared::cluster.v4.f32 [%0], {%1, %2, %3, %4};"
                         :: "r"(rx), "f"(sv.x), "f"(sv.y), "f"(sv.z), "f"(sv.w)
                         : "memory");
        }

        // arrive: cumulative release of this thread's DSMEM stores
        asm volatile("barrier.cluster.arrive.aligned;" ::: "memory");

        // overlap the barrier with history STG + noise prefetch (t+2)
        if (q == 0)
            outv[512 + (size_t)t * NREG + j] = make_float2(sE, sI);
        int t2 = t + 2; if (t2 >= NSTEPS) t2 = NSTEPS - 1;
        float vf = __ldg(vofT + (size_t)t2 * NREG + j);

        asm volatile("barrier.cluster.wait.aligned;" ::: "memory");

        vc = vn; vn = vf;
    }

    if (q == 0) outv[j] = make_float2(sE, sI);

    // drain: nobody exits while peers may still write our smem
    asm volatile("barrier.cluster.arrive.aligned;" ::: "memory");
    asm volatile("barrier.cluster.wait.aligned;"   ::: "memory");
}

extern "C" void kernel_launch(void* const* d_in, const int* in_sizes, int n_in,
                              void* d_out, int out_size) {
    const float* init = nullptr;
    const float* con  = nullptr;
    const float* v    = nullptr;
    for (int i = 0; i < n_in; ++i) {
        if      (in_sizes[i] == NREG * 2)      init = (const float*)d_in[i];
        else if (in_sizes[i] == NREG * NREG)   con  = (const float*)d_in[i];
        else if (in_sizes[i] == NSTEPS * NREG) v    = (const float*)d_in[i];
    }
    rww_kernel<<<NCTAS, NTHR, SMEM_BYTES>>>(init, con, v, (float*)d_out);
    (void)out_size;
}

// round 6
// speedup vs baseline: 2.8200x; 1.1665x over previous
#include <cuda_runtime.h>
#include <cstdint>
#include <cstddef>

// RWW whole-brain sim, 8-CTA cluster, Con_Mtx register-resident.
// R6: NO barrier.cluster in the loop. Per-step exchange via
//     cp.async.bulk.shared::cluster.shared::cta + mbarrier complete_tx:
//     each CTA stages its 64 new S_E (256 B) and one thread issues 8 bulk
//     copies (data + completion fused). Destinations receive only 8 HW-
//     aggregated tx updates per step on one mbarrier (expect_tx = 2048 B)
//     and wake via try_wait (~60 cyc) instead of UCGABAR (~490 cyc).
//     CTAs wait only for data -> skew decoupled.

#define NREG    512
#define NSTEPS  20000
#define NCTAS   8
#define NTHR    512

// x layout: eighth stride EF floats (272 B == 16 mod 128 -> conflict-free
// LDS.128 across the 8 column-eighth lane groups, 4-way broadcast within).
#define EF 68
#define PF 544                       // floats per parity buffer
#define XB      (2 * PF * 4)         // 4352 B : x buffers
#define STG_OFF XB                   // 2 x 256 B staging
#define MB_OFF  (XB + 512)           // 2 mbarriers (8 B each)
#define SMEM_BYTES (MB_OFF + 64)

__device__ __forceinline__ unsigned long long ffma2(
    unsigned long long a, unsigned long long b, unsigned long long c) {
    unsigned long long d;
    asm("fma.rn.f32x2 %0, %1, %2, %3;" : "=l"(d) : "l"(a), "l"(b), "l"(c));
    return d;
}
__device__ __forceinline__ float fsum2(unsigned long long a) {
    float2 f = *reinterpret_cast<float2*>(&a);
    return f.x + f.y;
}
__device__ __forceinline__ void mbar_wait(uint32_t mb, uint32_t par) {
    asm volatile(
        "{\n\t"
        ".reg .pred P;\n"
        "WL_%=:\n\t"
        "mbarrier.try_wait.parity.acquire.cluster.shared::cta.b64 P, [%0], %1, 0x989680;\n\t"
        "@!P bra WL_%=;\n\t"
        "}" :: "r"(mb), "r"(par) : "memory");
}

__device__ __forceinline__ float Hfun(float I, float a, float b, float d, float bigc) {
    float x     = fmaf(a, I, -b);
    float numer = fabsf(x) + 1e-9f;
    float neg   = -d * x;
    float e     = __expf(fminf(neg, 51.0f));
    float den_s = fabsf(1.0f - e) + 1e-9f * d;
    float den_b = fabsf(1.0f - bigc * neg) + 1e-9f * d;
    float denom = (neg > 50.0f) ? den_b : den_s;
    return __fdividef(numer, denom);
}

extern __shared__ float smx[];

__global__ void __launch_bounds__(NTHR, 1) __cluster_dims__(NCTAS, 1, 1)
rww_kernel(const float* __restrict__ init_state,   // (512, 2)
           const float* __restrict__ Con,          // (512, 512) row-major
           const float* __restrict__ vofT,         // (20000, 512)
           float* __restrict__ out)                // 1024 final + 20000*1024 hist
{
    const int tid  = (int)threadIdx.x;
    const int cta  = (int)blockIdx.x;          // cluster rank (grid = 1 cluster)
    const int r    = tid >> 3;                 // local row 0..63
    const int q    = tid & 7;                  // column eighth 0..7
    const int j    = cta * 64 + r;             // global region of this row

    uint32_t sb;
    asm("{ .reg .u64 t; cvta.to.shared.u64 t, %1; cvt.u32.u64 %0, t; }"
        : "=r"(sb) : "l"(smx));
    const uint32_t mb0 = sb + MB_OFF;
    const uint32_t mb1 = sb + MB_OFF + 8;

    // ---- mbarriers: count=1; arm both phases' tx at init ----
    if (tid == 0) {
        asm volatile("mbarrier.init.shared.b64 [%0], %1;" :: "r"(mb0), "r"(1));
        asm volatile("mbarrier.init.shared.b64 [%0], %1;" :: "r"(mb1), "r"(1));
        asm volatile("mbarrier.arrive.expect_tx.shared.b64 _, [%0], %1;"
                     :: "r"(mb0), "r"(2048) : "memory");
        asm volatile("mbarrier.arrive.expect_tx.shared.b64 _, [%0], %1;"
                     :: "r"(mb1), "r"(2048) : "memory");
    }

    // ---- Con row segment: cols q*64..q*64+63 -> 32 packed f32x2 regs ----
    unsigned long long c64[32];
    {
        const ulonglong2* src =
            (const ulonglong2*)(Con + (size_t)j * NREG + (size_t)q * 64);
        #pragma unroll
        for (int it = 0; it < 16; ++it) {
            ulonglong2 t2 = src[it];
            c64[2*it] = t2.x; c64[2*it+1] = t2.y;
        }
    }

    // ---- init x buffer 0 locally: x[k] @ (k>>6)*EF + (k&63) ----
    if (tid < NREG)
        smx[(tid >> 6) * EF + (tid & 63)] = init_state[2 * tid];

    float sE = init_state[2 * j];
    float sI = init_state[2 * j + 1];

    // peer smem base addresses (mapa once; offsets preserve the rank field)
    uint32_t remBase[NCTAS];
    #pragma unroll
    for (int d = 0; d < NCTAS; ++d)
        asm("mapa.shared::cluster.u32 %0, %1, %2;" : "=r"(remBase[d]) : "r"(sb), "r"(d));

    __syncthreads();

    // one-time rendezvous: all CTAs' barriers inited+armed, buffer 0 ready
    asm volatile("barrier.cluster.arrive.aligned;" ::: "memory");
    asm volatile("barrier.cluster.wait.aligned;"   ::: "memory");

    // noise pipeline, 2 deep
    float vc = __ldg(vofT + j);
    float vn = __ldg(vofT + NREG + j);
    float2* outv = (float2*)out;

    int ph0 = 0, ph1 = 0;

    for (int t = 0; t < NSTEPS; ++t) {
        const int b = t & 1;

        // ---- wait for this step's x data (skip t=0: local init) ----
        if (t) {
            const uint32_t mb = b ? mb1 : mb0;
            mbar_wait(mb, (uint32_t)(b ? ph1 : ph0));
            if (b) ph1 ^= 1; else ph0 ^= 1;
            if (tid == 0)   // re-arm this barrier's next phase
                asm volatile("mbarrier.arrive.expect_tx.shared.b64 _, [%0], %1;"
                             :: "r"(mb), "r"(2048) : "memory");
        }

        // ---- matvec: 64 cols/thread, Con in regs, x from smem (f32x2) ----
        const ulonglong2* x2 = (const ulonglong2*)
            ((const char*)smx + (b ? PF * 4 : 0) + q * (EF * 4));
        unsigned long long a0 = 0ULL, a1 = 0ULL, a2 = 0ULL, a3 = 0ULL;
        #pragma unroll
        for (int it = 0; it < 8; ++it) {
            ulonglong2 xa = x2[2*it];
            ulonglong2 xb = x2[2*it+1];
            a0 = ffma2(c64[4*it+0], xa.x, a0);
            a1 = ffma2(c64[4*it+1], xa.y, a1);
            a2 = ffma2(c64[4*it+2], xb.x, a2);
            a3 = ffma2(c64[4*it+3], xb.y, a3);
        }
        float acc = (fsum2(a0) + fsum2(a1)) + (fsum2(a2) + fsum2(a3));
        acc += __shfl_xor_sync(0xffffffffu, acc, 1);
        acc += __shfl_xor_sync(0xffffffffu, acc, 2);
        acc += __shfl_xor_sync(0xffffffffu, acc, 4);

        // ---- epilogue (replicated across the 8 lanes of the row) ----
        float I_E = 0.382f  + 0.21f * sE + 3.0f * acc - sI;   // LAMBDA=0 folded
        float I_I = 0.2674f + 0.15f * sE - sI;
        float rE = Hfun(I_E, 310.0f, 125.0f, 0.16f,  1e9f);
        float rI = Hfun(I_I, 615.0f, 177.0f, 0.087f, 1e5f);
        float dE = -sE * 0.01f + (1.0f - sE) * 6.41e-4f * rE + 0.01f * vc;
        float dI = -sI * 0.1f  + 1.0e-3f * rI + 0.01f * vc;
        sE = fmaf(1e-4f, dE, sE);
        sI = fmaf(1e-4f, dI, sI);

        // ---- stage this CTA's 64 new S_E values (double-buffered) ----
        if (q == 0)
            smx[STG_OFF / 4 + b * 64 + r] = sE;
        __syncthreads();

        // ---- one thread ships 8 bulk copies: data + completion fused ----
        if (tid == 0 && (t + 1 < NSTEPS)) {
            asm volatile("fence.proxy.async.shared::cta;" ::: "memory");
            const uint32_t src  = sb + (uint32_t)(STG_OFF + b * 256);
            const uint32_t xoff = (uint32_t)(((b ^ 1) * PF + cta * EF) * 4);
            const uint32_t moff = (uint32_t)(MB_OFF + ((b ^ 1) ? 8 : 0));
            #pragma unroll
            for (int d = 0; d < NCTAS; ++d) {
                uint32_t dst = remBase[d] + xoff;
                uint32_t rmb = remBase[d] + moff;
                asm volatile(
                    "cp.async.bulk.shared::cluster.shared::cta.mbarrier::complete_tx::bytes "
                    "[%0], [%1], %2, [%3];"
                    :: "r"(dst), "r"(src), "r"(256), "r"(rmb) : "memory");
            }
        }

        // off-critical-path: history STG + noise prefetch (t+2)
        if (q == 0)
            outv[512 + (size_t)t * NREG + j] = make_float2(sE, sI);
        int t2 = t + 2; if (t2 >= NSTEPS) t2 = NSTEPS - 1;
        float vf = __ldg(vofT + (size_t)t2 * NREG + j);

        vc = vn; vn = vf;
    }

    if (q == 0) outv[j] = make_float2(sE, sI);

    // drain: nobody exits while peers may still write our smem
    asm volatile("barrier.cluster.arrive.aligned;" ::: "memory");
    asm volatile("barrier.cluster.wait.aligned;"   ::: "memory");
}

extern "C" void kernel_launch(void* const* d_in, const int* in_sizes, int n_in,
                              void* d_out, int out_size) {
    const float* init = nullptr;
    const float* con  = nullptr;
    const float* v    = nullptr;
    for (int i = 0; i < n_in; ++i) {
        if      (in_sizes[i] == NREG * 2)      init = (const float*)d_in[i];
        else if (in_sizes[i] == NREG * NREG)   con  = (const float*)d_in[i];
        else if (in_sizes[i] == NSTEPS * NREG) v    = (const float*)d_in[i];
    }
    rww_kernel<<<NCTAS, NTHR, SMEM_BYTES>>>(init, con, v, (float*)d_out);
    (void)out_size;
}